// round 6
// baseline (speedup 1.0000x reference)
#include <cuda_runtime.h>

// Problem dims (fixed by the dataset)
#define B_  8
#define N_  10000
#define E_  160000
#define F_  128
#define H_  256
#define NG  (B_ * N_)   // 80000 total nodes
#define NE  (B_ * E_)   // 1280000 total edges

// ---------------- static scratch (no allocations allowed) ----------------
__device__ __align__(16) float g_xw  [NG * F_];   // x @ Wc            (41 MB)
__device__ __align__(16) float g_xres[NG * F_];   // relu(agg+bc)+x0   (41 MB)
__device__ __align__(16) float g_h1  [NG * H_];   // hidden after W1   (82 MB)
__device__ int   g_cnt [NG];        // in-degree (excl self loop)
__device__ float g_dinv[NG];        // rsqrt(deg)
__device__ int   g_off [NG + 1];    // CSR offsets
__device__ int   g_cur [NG];        // fill cursors
__device__ int   g_esrc[NE];        // CSR source node per in-edge
__device__ int   g_is64;            // 1 if edge_index is int64, 0 if int32

// ---------------- dtype probe ----------------
// If int64 with values in [0,10000), all high words are 0. If int32, odd
// 32-bit words are random node ids. Scan only the first NE 64-bit slots
// (= NE*8 bytes <= int32 buffer size of 2*NE*4 bytes) to stay in bounds.
__global__ void init_flag_kernel() { g_is64 = 1; }

__global__ void detect_kernel(const unsigned* __restrict__ w) {
    int i = blockIdx.x * blockDim.x + threadIdx.x;
    if (i < NE && w[2 * i + 1] != 0u) g_is64 = 0;
}

// ---------------- CSR construction ----------------
__global__ void zero_cnt_kernel() {
    int i = blockIdx.x * blockDim.x + threadIdx.x;
    if (i < NG) g_cnt[i] = 0;
}

__device__ __forceinline__ int load_edge(const void* eiv, size_t pos) {
    if (g_is64) return (int)((const long long*)eiv)[pos];
    return ((const int*)eiv)[pos];
}

__global__ void count_kernel(const void* __restrict__ eiv) {
    int idx = blockIdx.x * blockDim.x + threadIdx.x;
    if (idx >= NE) return;
    int b = idx / E_;
    int e = idx - b * E_;
    int dst = load_edge(eiv, (size_t)b * 2 * E_ + E_ + e);
    atomicAdd(&g_cnt[b * N_ + dst], 1);
}

// Single-block exclusive scan over 80000 ints (each thread owns a contiguous chunk)
__global__ void scan_kernel() {
    __shared__ int part[1024];
    const int tid = threadIdx.x;
    const int CH  = (NG + 1023) / 1024;   // 79
    int start = tid * CH;
    int end   = start + CH; if (end > NG) end = NG;
    int s = 0;
    for (int i = start; i < end; i++) s += g_cnt[i];
    part[tid] = s;
    __syncthreads();
    // inclusive Hillis-Steele scan of per-thread partials
    for (int off = 1; off < 1024; off <<= 1) {
        int v = (tid >= off) ? part[tid - off] : 0;
        __syncthreads();
        part[tid] += v;
        __syncthreads();
    }
    int run = (tid > 0) ? part[tid - 1] : 0;
    for (int i = start; i < end; i++) {
        g_off[i] = run;
        g_cur[i] = run;
        run += g_cnt[i];
    }
    if (tid == 1023) g_off[NG] = part[1023];
}

__global__ void dinv_kernel() {
    int i = blockIdx.x * blockDim.x + threadIdx.x;
    if (i < NG) g_dinv[i] = rsqrtf((float)(g_cnt[i] + 1));  // +1 self loop
}

__global__ void fill_kernel(const void* __restrict__ eiv) {
    int idx = blockIdx.x * blockDim.x + threadIdx.x;
    if (idx >= NE) return;
    int b = idx / E_;
    int e = idx - b * E_;
    size_t base = (size_t)b * 2 * E_;
    int src = load_edge(eiv, base + e);
    int dst = load_edge(eiv, base + E_ + e);
    int pos = atomicAdd(&g_cur[b * N_ + dst], 1);
    g_esrc[pos] = b * N_ + src;
}

// ---------------- aggregation gather (warp per destination node) ----------
// computes xres = relu(agg + bc) + x0, where
// agg[g] = dinv[g]^2 * xw[g] + sum_e dinv[src]*dinv[g] * xw[src]
__global__ __launch_bounds__(256) void gather_kernel(const float* __restrict__ x0,
                                                     const float* __restrict__ bc) {
    int warp = (blockIdx.x * blockDim.x + threadIdx.x) >> 5;
    int lane = threadIdx.x & 31;
    if (warp >= NG) return;

    const float4* xw4 = (const float4*)g_xw;
    float di = g_dinv[warp];

    float4 v  = xw4[(size_t)warp * 32 + lane];
    float  w0 = di * di;
    float4 acc;
    acc.x = w0 * v.x; acc.y = w0 * v.y; acc.z = w0 * v.z; acc.w = w0 * v.w;

    int e0 = g_off[warp], e1 = g_off[warp + 1];
    for (int e = e0; e < e1; e++) {
        int   s = g_esrc[e];
        float w = di * g_dinv[s];
        float4 u = xw4[(size_t)s * 32 + lane];
        acc.x += w * u.x; acc.y += w * u.y; acc.z += w * u.z; acc.w += w * u.w;
    }

    float4 b4  = ((const float4*)bc)[lane];
    float4 r4  = ((const float4*)x0)[(size_t)warp * 32 + lane];
    float4 out;
    out.x = fmaxf(acc.x + b4.x, 0.f) + r4.x;
    out.y = fmaxf(acc.y + b4.y, 0.f) + r4.y;
    out.z = fmaxf(acc.z + b4.z, 0.f) + r4.z;
    out.w = fmaxf(acc.w + b4.w, 0.f) + r4.w;
    ((float4*)g_xres)[(size_t)warp * 32 + lane] = out;
}

// ---------------- SGEMM: 128x128 tile, 256 threads, 8x8 per thread ----------
// C[M,N] = act(A[M,K] @ B[K,N] + bias).  ACT: 0 = none/no-bias, 1 = bias+leaky_relu
template <int ACT>
__global__ __launch_bounds__(256) void sgemm_k(const float* __restrict__ A,
                                               const float* __restrict__ Bm,
                                               const float* __restrict__ bias,
                                               float* __restrict__ C,
                                               int M, int Nn, int K) {
    __shared__ float As[8][128];
    __shared__ float Bs[8][128];

    const int tx   = threadIdx.x;
    const int brow = blockIdx.y * 128;
    const int bcol = blockIdx.x * 128;

    const int aRow = tx >> 1;          // 0..127
    const int aCol = (tx & 1) * 4;     // 0 or 4
    const int bRow = tx >> 5;          // 0..7
    const int bCol = (tx & 31) * 4;    // 0..124

    const int ty = tx >> 4;            // 0..15 -> row group
    const int tc = tx & 15;            // 0..15 -> col group

    float acc[8][8];
#pragma unroll
    for (int i = 0; i < 8; i++)
#pragma unroll
        for (int j = 0; j < 8; j++) acc[i][j] = 0.f;

    const float* Aptr = A  + (size_t)(brow + aRow) * K + aCol;
    const float* Bptr = Bm + (size_t)bRow * Nn + bcol + bCol;

    for (int k0 = 0; k0 < K; k0 += 8) {
        float4 a = *(const float4*)(Aptr + k0);
        As[aCol + 0][aRow] = a.x;
        As[aCol + 1][aRow] = a.y;
        As[aCol + 2][aRow] = a.z;
        As[aCol + 3][aRow] = a.w;
        float4 b = *(const float4*)(Bptr + (size_t)k0 * Nn);
        *(float4*)&Bs[bRow][bCol] = b;
        __syncthreads();

#pragma unroll
        for (int kk = 0; kk < 8; kk++) {
            float ar[8], br[8];
            *(float4*)(ar)     = *(const float4*)&As[kk][ty * 8];
            *(float4*)(ar + 4) = *(const float4*)&As[kk][ty * 8 + 4];
            *(float4*)(br)     = *(const float4*)&Bs[kk][tc * 8];
            *(float4*)(br + 4) = *(const float4*)&Bs[kk][tc * 8 + 4];
#pragma unroll
            for (int i = 0; i < 8; i++)
#pragma unroll
                for (int j = 0; j < 8; j++) acc[i][j] += ar[i] * br[j];
        }
        __syncthreads();
    }

    // epilogue
    float bv[8];
    if (ACT == 1) {
#pragma unroll
        for (int j = 0; j < 8; j++) bv[j] = bias[bcol + tc * 8 + j];
    }
#pragma unroll
    for (int i = 0; i < 8; i++) {
        int row = brow + ty * 8 + i;
#pragma unroll
        for (int j = 0; j < 8; j += 4) {
            float4 v;
            float e0 = acc[i][j + 0], e1 = acc[i][j + 1], e2 = acc[i][j + 2], e3 = acc[i][j + 3];
            if (ACT == 1) {
                e0 += bv[j + 0]; e1 += bv[j + 1]; e2 += bv[j + 2]; e3 += bv[j + 3];
                e0 = (e0 > 0.f) ? e0 : 0.01f * e0;
                e1 = (e1 > 0.f) ? e1 : 0.01f * e1;
                e2 = (e2 > 0.f) ? e2 : 0.01f * e2;
                e3 = (e3 > 0.f) ? e3 : 0.01f * e3;
            }
            v.x = e0; v.y = e1; v.z = e2; v.w = e3;
            *(float4*)&C[(size_t)row * Nn + bcol + tc * 8 + j] = v;
        }
    }
}

// ---------------- launch ----------------
extern "C" void kernel_launch(void* const* d_in, const int* in_sizes, int n_in,
                              void* d_out, int out_size) {
    const float* x0  = (const float*)d_in[0];   // [B,N,F]
    const void*  ei  = d_in[1];                 // [B,2,E] int32 OR int64
    const float* Wc  = (const float*)d_in[2];   // [F,F]
    const float* bc  = (const float*)d_in[3];   // [F]
    const float* W1  = (const float*)d_in[4];   // [F,H]
    const float* b1  = (const float*)d_in[5];   // [H]
    const float* W2  = (const float*)d_in[6];   // [H,H]
    const float* b2  = (const float*)d_in[7];   // [H]
    float*       out = (float*)d_out;           // [B,N,H]

    float *p_xw, *p_xres, *p_h1;
    cudaGetSymbolAddress((void**)&p_xw,   g_xw);
    cudaGetSymbolAddress((void**)&p_xres, g_xres);
    cudaGetSymbolAddress((void**)&p_h1,   g_h1);

    // dtype probe (int32 vs int64 edge_index)
    init_flag_kernel<<<1, 1>>>();
    detect_kernel<<<(NE + 255) / 256, 256>>>((const unsigned*)ei);

    // CSR build
    zero_cnt_kernel<<<(NG + 255) / 256, 256>>>();
    count_kernel<<<(NE + 255) / 256, 256>>>(ei);
    scan_kernel<<<1, 1024>>>();
    dinv_kernel<<<(NG + 255) / 256, 256>>>();
    fill_kernel<<<(NE + 255) / 256, 256>>>(ei);

    // xw = x0 @ Wc   (M=80000, N=128, K=128)
    {
        dim3 grid(F_ / 128, NG / 128);
        sgemm_k<0><<<grid, 256>>>(x0, Wc, nullptr, p_xw, NG, F_, F_);
    }

    // xres = relu(agg + bc) + x0  (warp per node)
    gather_kernel<<<NG / 8, 256>>>(x0, bc);

    // h1 = leaky(xres @ W1 + b1)   (M=80000, N=256, K=128)
    {
        dim3 grid(H_ / 128, NG / 128);
        sgemm_k<1><<<grid, 256>>>(p_xres, W1, b1, p_h1, NG, H_, F_);
    }

    // out = leaky(h1 @ W2 + b2)    (M=80000, N=256, K=256)
    {
        dim3 grid(H_ / 128, NG / 128);
        sgemm_k<1><<<grid, 256>>>(p_h1, W2, b2, out, NG, H_, H_);
    }
}

// round 9
// speedup vs baseline: 1.4282x; 1.4282x over previous
#include <cuda_runtime.h>
#include <cuda_bf16.h>
#include <cstdint>

// Problem dims (fixed by the dataset)
#define B_  8
#define N_  10000
#define E_  160000
#define F_  128
#define H_  256
#define NG  (B_ * N_)   // 80000 total nodes
#define NE  (B_ * E_)   // 1280000 total edges

// ---------------- static scratch (no allocations allowed) ----------------
__device__ __align__(16) float          g_xw [NG * F_];       // x @ Wc (fp32, for gather)
__device__ __align__(16) __nv_bfloat16  g_x0p[NG * 3 * F_];   // x0 tripled split [hi|hi|lo]
__device__ __align__(16) __nv_bfloat16  g_xrp[NG * 3 * F_];   // xres tripled split
__device__ __align__(16) __nv_bfloat16  g_h1p[NG * 3 * H_];   // h1 tripled split
// weights transposed+split: B'[n][k'] with k' = [hi(K)|lo(K)|hi(K)]
__device__ __align__(16) __nv_bfloat16  g_wcp[F_ * 3 * F_];
__device__ __align__(16) __nv_bfloat16  g_w1p[H_ * 3 * F_];
__device__ __align__(16) __nv_bfloat16  g_w2p[H_ * 3 * H_];

__device__ int   g_cnt [NG];
__device__ float g_dinv[NG];
__device__ int   g_off [NG + 1];
__device__ int   g_cur [NG];
__device__ int   g_esrc[NE];
__device__ int   g_is64;

// ================= helpers =================
__device__ __forceinline__ uint32_t smem_u32(const void* p) {
    uint32_t a;
    asm("{ .reg .u64 t; cvta.to.shared.u64 t, %1; cvt.u32.u64 %0, t; }" : "=r"(a) : "l"(p));
    return a;
}
__device__ __forceinline__ void cp16(uint32_t dst, const void* src) {
    asm volatile("cp.async.cg.shared.global [%0], [%1], 16;" :: "r"(dst), "l"(src) : "memory");
}
__device__ __forceinline__ void cpcommit() {
    asm volatile("cp.async.commit_group;" ::: "memory");
}
template <int Nw> __device__ __forceinline__ void cpwait() {
    asm volatile("cp.async.wait_group %0;" :: "n"(Nw) : "memory");
}
__device__ __forceinline__ void ldm4(uint32_t* r, uint32_t addr) {
    asm volatile("ldmatrix.sync.aligned.m8n8.x4.shared.b16 {%0,%1,%2,%3}, [%4];"
        : "=r"(r[0]), "=r"(r[1]), "=r"(r[2]), "=r"(r[3]) : "r"(addr));
}
__device__ __forceinline__ void mma_bf16(float* c, const uint32_t* a, uint32_t b0, uint32_t b1) {
    asm volatile(
        "mma.sync.aligned.m16n8k16.row.col.f32.bf16.bf16.f32 "
        "{%0,%1,%2,%3}, {%4,%5,%6,%7}, {%8,%9}, {%0,%1,%2,%3};"
        : "+f"(c[0]), "+f"(c[1]), "+f"(c[2]), "+f"(c[3])
        : "r"(a[0]), "r"(a[1]), "r"(a[2]), "r"(a[3]), "r"(b0), "r"(b1));
}
__device__ __forceinline__ uint32_t pack_bf2(__nv_bfloat16 a, __nv_bfloat16 b) {
    __nv_bfloat162 h2(a, b);
    return *reinterpret_cast<uint32_t*>(&h2);
}
__device__ __forceinline__ void split1(float v, __nv_bfloat16& h, __nv_bfloat16& l) {
    h = __float2bfloat16(v);
    l = __float2bfloat16(v - __bfloat162float(h));
}

// ---------------- dtype probe ----------------
__global__ void init_flag_kernel() { g_is64 = 1; }
__global__ void detect_kernel(const unsigned* __restrict__ w) {
    int i = blockIdx.x * blockDim.x + threadIdx.x;
    if (i < NE && w[2 * i + 1] != 0u) g_is64 = 0;
}

// ---------------- CSR construction ----------------
__global__ void zero_cnt_kernel() {
    int i = blockIdx.x * blockDim.x + threadIdx.x;
    if (i < NG) g_cnt[i] = 0;
}
__device__ __forceinline__ int load_edge(const void* eiv, size_t pos) {
    if (g_is64) return (int)((const long long*)eiv)[pos];
    return ((const int*)eiv)[pos];
}
__global__ void count_kernel(const void* __restrict__ eiv) {
    int idx = blockIdx.x * blockDim.x + threadIdx.x;
    if (idx >= NE) return;
    int b = idx / E_;
    int e = idx - b * E_;
    int dst = load_edge(eiv, (size_t)b * 2 * E_ + E_ + e);
    atomicAdd(&g_cnt[b * N_ + dst], 1);
}
__global__ void scan_kernel() {
    __shared__ int part[1024];
    const int tid = threadIdx.x;
    const int CH  = (NG + 1023) / 1024;
    int start = tid * CH;
    int end   = start + CH; if (end > NG) end = NG;
    int s = 0;
    for (int i = start; i < end; i++) s += g_cnt[i];
    part[tid] = s;
    __syncthreads();
    for (int off = 1; off < 1024; off <<= 1) {
        int v = (tid >= off) ? part[tid - off] : 0;
        __syncthreads();
        part[tid] += v;
        __syncthreads();
    }
    int run = (tid > 0) ? part[tid - 1] : 0;
    for (int i = start; i < end; i++) {
        g_off[i] = run;
        g_cur[i] = run;
        run += g_cnt[i];
    }
    if (tid == 1023) g_off[NG] = part[1023];
}
__global__ void dinv_kernel() {
    int i = blockIdx.x * blockDim.x + threadIdx.x;
    if (i < NG) g_dinv[i] = rsqrtf((float)(g_cnt[i] + 1));
}
__global__ void fill_kernel(const void* __restrict__ eiv) {
    int idx = blockIdx.x * blockDim.x + threadIdx.x;
    if (idx >= NE) return;
    int b = idx / E_;
    int e = idx - b * E_;
    size_t base = (size_t)b * 2 * E_;
    int src = load_edge(eiv, base + e);
    int dst = load_edge(eiv, base + E_ + e);
    int pos = atomicAdd(&g_cur[b * N_ + dst], 1);
    g_esrc[pos] = b * N_ + src;
}

// ---------------- x0 tripled split: [hi(F)|hi(F)|lo(F)] per row ------------
__global__ void split_x0_kernel(const float* __restrict__ x0) {
    int i = blockIdx.x * blockDim.x + threadIdx.x;   // over NG*F/4
    if (i >= NG * F_ / 4) return;
    int row = i >> 5;                  // F/4 = 32 quads per row
    int col = (i & 31) * 4;
    float4 v = ((const float4*)x0)[i];
    __nv_bfloat16 h0, h1, h2, h3, l0, l1, l2, l3;
    split1(v.x, h0, l0); split1(v.y, h1, l1); split1(v.z, h2, l2); split1(v.w, h3, l3);
    uint2 hw = make_uint2(pack_bf2(h0, h1), pack_bf2(h2, h3));
    uint2 lw = make_uint2(pack_bf2(l0, l1), pack_bf2(l2, l3));
    size_t base = (size_t)row * (3 * F_) + col;
    *(uint2*)&g_x0p[base]            = hw;
    *(uint2*)&g_x0p[base + F_]       = hw;
    *(uint2*)&g_x0p[base + 2 * F_]   = lw;
}

// ---------------- weight transpose + tripled split -------------------------
// B'[n][k'] where k' = [hi(K) | lo(K) | hi(K)], B'[n][k] = split(W[k][n])
__global__ void wsplit_kernel(const float* __restrict__ W, __nv_bfloat16* __restrict__ T,
                              int K, int Nn) {
    int i = blockIdx.x * blockDim.x + threadIdx.x;
    if (i >= K * Nn) return;
    int n = i / K, k = i - n * K;
    float v = W[(size_t)k * Nn + n];
    __nv_bfloat16 h, l;
    split1(v, h, l);
    size_t base = (size_t)n * (3 * K);
    T[base + k]         = h;
    T[base + K + k]     = l;
    T[base + 2 * K + k] = h;
}

// ---------------- aggregation gather (warp per destination node) -----------
// xres = relu(agg + bc) + x0  -> tripled split [hi|hi|lo]
__global__ __launch_bounds__(256) void gather_kernel(const float* __restrict__ x0,
                                                     const float* __restrict__ bc) {
    int warp = (blockIdx.x * blockDim.x + threadIdx.x) >> 5;
    int lane = threadIdx.x & 31;
    if (warp >= NG) return;

    const float4* xw4 = (const float4*)g_xw;
    float di = g_dinv[warp];

    float4 v  = xw4[(size_t)warp * 32 + lane];
    float  w0 = di * di;
    float4 acc;
    acc.x = w0 * v.x; acc.y = w0 * v.y; acc.z = w0 * v.z; acc.w = w0 * v.w;

    int e0 = g_off[warp], e1 = g_off[warp + 1];
    for (int e = e0; e < e1; e++) {
        int   s = g_esrc[e];
        float w = di * g_dinv[s];
        float4 u = xw4[(size_t)s * 32 + lane];
        acc.x += w * u.x; acc.y += w * u.y; acc.z += w * u.z; acc.w += w * u.w;
    }

    float4 b4 = ((const float4*)bc)[lane];
    float4 r4 = ((const float4*)x0)[(size_t)warp * 32 + lane];
    float o0 = fmaxf(acc.x + b4.x, 0.f) + r4.x;
    float o1 = fmaxf(acc.y + b4.y, 0.f) + r4.y;
    float o2 = fmaxf(acc.z + b4.z, 0.f) + r4.z;
    float o3 = fmaxf(acc.w + b4.w, 0.f) + r4.w;

    __nv_bfloat16 h0, h1, h2, h3, l0, l1, l2, l3;
    split1(o0, h0, l0); split1(o1, h1, l1); split1(o2, h2, l2); split1(o3, h3, l3);
    uint2 hw = make_uint2(pack_bf2(h0, h1), pack_bf2(h2, h3));
    uint2 lw = make_uint2(pack_bf2(l0, l1), pack_bf2(l2, l3));
    size_t base = (size_t)warp * (3 * F_) + lane * 4;
    *(uint2*)&g_xrp[base]          = hw;
    *(uint2*)&g_xrp[base + F_]     = hw;
    *(uint2*)&g_xrp[base + 2 * F_] = lw;
}

// ================= HMMA bf16 GEMM (mma.sync, sm_80 baseline features) ======
// C[M,N] = act(A' @ B'^T + bias); A' [M,Kp] row-major bf16 (tripled split),
// B' [N,Kp] row-major bf16. CTA tile 128x128, 8 warps of 64x32, k-chunk 32,
// double-buffered cp.async. Smem row stride 40 bf16 (80 B) -> ldmatrix
// conflict-free.
// EPI: 0 = plain fp32 out; 1 = bias+leaky -> tripled-split bf16 out (row
//      stride 3*Nn, [hi|hi|lo]); 2 = bias+leaky -> fp32 out.
#define TILE_BYTES_ 10240          // 128 rows * 80 B
#define STAGE_BYTES_ 20480         // A tile + B tile

template <int EPI>
__global__ __launch_bounds__(256) void gemm_bf16(
    const __nv_bfloat16* __restrict__ Ap, const __nv_bfloat16* __restrict__ Bp,
    const float* __restrict__ bias, float* __restrict__ Cf,
    __nv_bfloat16* __restrict__ Cbf, int Nn, int Kp)
{
    __shared__ __align__(16) char smem[2 * STAGE_BYTES_];
    const int tid  = threadIdx.x;
    const int w    = tid >> 5;
    const int lane = tid & 31;
    const int m0 = blockIdx.y * 128;
    const int n0 = blockIdx.x * 128;
    const int m0w = (w >> 2) * 64;   // 2 warps in M
    const int n0w = (w & 3) * 32;    // 4 warps in N

    const uint32_t sb = smem_u32(smem);

    float acc[4][4][4];
#pragma unroll
    for (int a = 0; a < 4; a++)
#pragma unroll
        for (int b = 0; b < 4; b++)
#pragma unroll
            for (int q = 0; q < 4; q++) acc[a][b][q] = 0.f;

    // per-thread load assignment: 512 16B chunks per tile, 2 per thread
    const int lrow0 = tid >> 2;            // rows 0..63
    const int loff  = (tid & 3) * 8;       // bf16 elems 0,8,16,24

    // ldmatrix per-lane address selectors
    const int grp = lane >> 3, lr = lane & 7;
    const uint32_t aSel = (uint32_t)((m0w + (grp & 1) * 8 + lr) * 80 + (grp >> 1) * 16);
    const uint32_t bSel = (uint32_t)((n0w + ((grp >> 1) & 1) * 8 + lr) * 80 + (grp & 1) * 16);

    const int nk = Kp >> 5;

#define PREFETCH(kc, st)                                                          \
    {                                                                             \
        const int k0_ = (kc) << 5;                                                \
        _Pragma("unroll")                                                         \
        for (int i_ = 0; i_ < 2; i_++) {                                          \
            int row_ = lrow0 + i_ * 64;                                           \
            cp16(sb + (st) * STAGE_BYTES_ + row_ * 80 + loff * 2,                 \
                 Ap + (size_t)(m0 + row_) * Kp + k0_ + loff);                     \
            cp16(sb + (st) * STAGE_BYTES_ + TILE_BYTES_ + row_ * 80 + loff * 2,   \
                 Bp + (size_t)(n0 + row_) * Kp + k0_ + loff);                     \
        }                                                                         \
        cpcommit();                                                               \
    }

    PREFETCH(0, 0);

    for (int kc = 0; kc < nk; kc++) {
        const int st = kc & 1;
        if (kc + 1 < nk) { PREFETCH(kc + 1, st ^ 1); cpwait<1>(); }
        else             { cpwait<0>(); }
        __syncthreads();

        const uint32_t aBase = sb + st * STAGE_BYTES_ + aSel;
        const uint32_t bBase = sb + st * STAGE_BYTES_ + TILE_BYTES_ + bSel;
#pragma unroll
        for (int ks = 0; ks < 2; ks++) {
            uint32_t a[4][4], b[2][4];
#pragma unroll
            for (int mi = 0; mi < 4; mi++)
                ldm4(a[mi], aBase + mi * 16 * 80 + ks * 32);
#pragma unroll
            for (int nj = 0; nj < 2; nj++)
                ldm4(b[nj], bBase + nj * 16 * 80 + ks * 32);
#pragma unroll
            for (int mi = 0; mi < 4; mi++)
#pragma unroll
                for (int nf = 0; nf < 4; nf++)
                    mma_bf16(acc[mi][nf], a[mi],
                             b[nf >> 1][(nf & 1) * 2], b[nf >> 1][(nf & 1) * 2 + 1]);
        }
        __syncthreads();
    }
#undef PREFETCH

    // ---- epilogue ----
    const int r0 = lane >> 2;
    const int cc = (lane & 3) * 2;
    const int rs = 3 * Nn;   // tripled-split row stride for EPI 1
#pragma unroll
    for (int mi = 0; mi < 4; mi++) {
        const int row1 = m0 + m0w + mi * 16 + r0;
        const int row2 = row1 + 8;
#pragma unroll
        for (int nf = 0; nf < 4; nf++) {
            const int col = n0 + n0w + nf * 8 + cc;
            float v0 = acc[mi][nf][0], v1 = acc[mi][nf][1];
            float v2 = acc[mi][nf][2], v3 = acc[mi][nf][3];
            if (EPI >= 1) {
                float bb0 = bias[col], bb1 = bias[col + 1];
                v0 += bb0; v1 += bb1; v2 += bb0; v3 += bb1;
                v0 = (v0 > 0.f) ? v0 : 0.01f * v0;
                v1 = (v1 > 0.f) ? v1 : 0.01f * v1;
                v2 = (v2 > 0.f) ? v2 : 0.01f * v2;
                v3 = (v3 > 0.f) ? v3 : 0.01f * v3;
            }
            if (EPI == 1) {
                __nv_bfloat16 h0, h1, h2, h3, l0, l1, l2, l3;
                split1(v0, h0, l0); split1(v1, h1, l1);
                split1(v2, h2, l2); split1(v3, h3, l3);
                uint32_t hiA = pack_bf2(h0, h1), loA = pack_bf2(l0, l1);
                uint32_t hiB = pack_bf2(h2, h3), loB = pack_bf2(l2, l3);
                size_t b1a = (size_t)row1 * rs + col;
                size_t b2a = (size_t)row2 * rs + col;
                *(uint32_t*)&Cbf[b1a]            = hiA;
                *(uint32_t*)&Cbf[b1a + Nn]       = hiA;
                *(uint32_t*)&Cbf[b1a + 2 * Nn]   = loA;
                *(uint32_t*)&Cbf[b2a]            = hiB;
                *(uint32_t*)&Cbf[b2a + Nn]       = hiB;
                *(uint32_t*)&Cbf[b2a + 2 * Nn]   = loB;
            } else {
                *(float2*)&Cf[(size_t)row1 * Nn + col] = make_float2(v0, v1);
                *(float2*)&Cf[(size_t)row2 * Nn + col] = make_float2(v2, v3);
            }
        }
    }
}

// ---------------- launch ----------------
extern "C" void kernel_launch(void* const* d_in, const int* in_sizes, int n_in,
                              void* d_out, int out_size) {
    const float* x0  = (const float*)d_in[0];   // [B,N,F]
    const void*  ei  = d_in[1];                 // [B,2,E] int32 OR int64
    const float* Wc  = (const float*)d_in[2];   // [F,F]
    const float* bc  = (const float*)d_in[3];   // [F]
    const float* W1  = (const float*)d_in[4];   // [F,H]
    const float* b1  = (const float*)d_in[5];   // [H]
    const float* W2  = (const float*)d_in[6];   // [H,H]
    const float* b2  = (const float*)d_in[7];   // [H]
    float*       out = (float*)d_out;           // [B,N,H]

    float* p_xw;
    __nv_bfloat16 *p_x0p, *p_xrp, *p_h1p, *p_wcp, *p_w1p, *p_w2p;
    cudaGetSymbolAddress((void**)&p_xw,  g_xw);
    cudaGetSymbolAddress((void**)&p_x0p, g_x0p);
    cudaGetSymbolAddress((void**)&p_xrp, g_xrp);
    cudaGetSymbolAddress((void**)&p_h1p, g_h1p);
    cudaGetSymbolAddress((void**)&p_wcp, g_wcp);
    cudaGetSymbolAddress((void**)&p_w1p, g_w1p);
    cudaGetSymbolAddress((void**)&p_w2p, g_w2p);

    // dtype probe
    init_flag_kernel<<<1, 1>>>();
    detect_kernel<<<(NE + 255) / 256, 256>>>((const unsigned*)ei);

    // CSR build
    zero_cnt_kernel<<<(NG + 255) / 256, 256>>>();
    count_kernel<<<(NE + 255) / 256, 256>>>(ei);
    scan_kernel<<<1, 1024>>>();
    dinv_kernel<<<(NG + 255) / 256, 256>>>();
    fill_kernel<<<(NE + 255) / 256, 256>>>(ei);

    // operand prep
    split_x0_kernel<<<(NG * F_ / 4 + 255) / 256, 256>>>(x0);
    wsplit_kernel<<<(F_ * F_ + 255) / 256, 256>>>(Wc, p_wcp, F_, F_);
    wsplit_kernel<<<(F_ * H_ + 255) / 256, 256>>>(W1, p_w1p, F_, H_);
    wsplit_kernel<<<(H_ * H_ + 255) / 256, 256>>>(W2, p_w2p, H_, H_);

    // xw = x0 @ Wc   (fp32 out, no bias)  M=80000 N=128 K'=384
    {
        dim3 grid(F_ / 128, NG / 128);
        gemm_bf16<0><<<grid, 256>>>(p_x0p, p_wcp, nullptr, p_xw, nullptr, F_, 3 * F_);
    }

    // xres = relu(agg + bc) + x0 -> tripled split
    gather_kernel<<<NG / 8, 256>>>(x0, bc);

    // h1 = leaky(xres @ W1 + b1) -> tripled split   M=80000 N=256 K'=384
    {
        dim3 grid(H_ / 128, NG / 128);
        gemm_bf16<1><<<grid, 256>>>(p_xrp, p_w1p, b1, nullptr, p_h1p, H_, 3 * F_);
    }

    // out = leaky(h1 @ W2 + b2) -> fp32   M=80000 N=256 K'=768
    {
        dim3 grid(H_ / 128, NG / 128);
        gemm_bf16<2><<<grid, 256>>>(p_h1p, p_w2p, b2, out, nullptr, H_, 3 * H_);
    }
}

// round 11
// speedup vs baseline: 1.4710x; 1.0300x over previous
#include <cuda_runtime.h>
#include <cuda_bf16.h>
#include <cstdint>

// Problem dims (fixed by the dataset)
#define B_  8
#define N_  10000
#define E_  160000
#define F_  128
#define H_  256
#define NG  (B_ * N_)   // 80000 total nodes
#define NE  (B_ * E_)   // 1280000 total edges

// ---------------- static scratch (no allocations allowed) ----------------
__device__ __align__(16) float          g_xw [NG * F_];       // x @ Wc (fp32, for gather)
__device__ __align__(16) __nv_bfloat16  g_x0p[NG * 2 * F_];   // x0 split [hi|lo]
__device__ __align__(16) __nv_bfloat16  g_xrp[NG * 2 * F_];   // xres split [hi|lo]
__device__ __align__(16) __nv_bfloat16  g_h1p[NG * 2 * H_];   // h1 split [hi|lo]
// weights transposed+split (tripled): B'[n][k'] with k' = [hi(K)|lo(K)|hi(K)]
__device__ __align__(16) __nv_bfloat16  g_wcp[F_ * 3 * F_];
__device__ __align__(16) __nv_bfloat16  g_w1p[H_ * 3 * F_];
__device__ __align__(16) __nv_bfloat16  g_w2p[H_ * 3 * H_];

__device__ int   g_cnt [NG];
__device__ float g_dinv[NG];
__device__ int   g_off [NG + 1];
__device__ int   g_cur [NG];
__device__ int   g_esrc[NE];
__device__ int   g_is64;

// ================= helpers =================
__device__ __forceinline__ uint32_t smem_u32(const void* p) {
    uint32_t a;
    asm("{ .reg .u64 t; cvta.to.shared.u64 t, %1; cvt.u32.u64 %0, t; }" : "=r"(a) : "l"(p));
    return a;
}
__device__ __forceinline__ void cp16(uint32_t dst, const void* src) {
    asm volatile("cp.async.cg.shared.global [%0], [%1], 16;" :: "r"(dst), "l"(src) : "memory");
}
__device__ __forceinline__ void cpcommit() {
    asm volatile("cp.async.commit_group;" ::: "memory");
}
template <int Nw> __device__ __forceinline__ void cpwait() {
    asm volatile("cp.async.wait_group %0;" :: "n"(Nw) : "memory");
}
__device__ __forceinline__ void ldm4(uint32_t* r, uint32_t addr) {
    asm volatile("ldmatrix.sync.aligned.m8n8.x4.shared.b16 {%0,%1,%2,%3}, [%4];"
        : "=r"(r[0]), "=r"(r[1]), "=r"(r[2]), "=r"(r[3]) : "r"(addr));
}
__device__ __forceinline__ void mma_bf16(float* c, const uint32_t* a, uint32_t b0, uint32_t b1) {
    asm volatile(
        "mma.sync.aligned.m16n8k16.row.col.f32.bf16.bf16.f32 "
        "{%0,%1,%2,%3}, {%4,%5,%6,%7}, {%8,%9}, {%0,%1,%2,%3};"
        : "+f"(c[0]), "+f"(c[1]), "+f"(c[2]), "+f"(c[3])
        : "r"(a[0]), "r"(a[1]), "r"(a[2]), "r"(a[3]), "r"(b0), "r"(b1));
}
__device__ __forceinline__ uint32_t pack_bf2(__nv_bfloat16 a, __nv_bfloat16 b) {
    __nv_bfloat162 h2(a, b);
    return *reinterpret_cast<uint32_t*>(&h2);
}
__device__ __forceinline__ void split1(float v, __nv_bfloat16& h, __nv_bfloat16& l) {
    h = __float2bfloat16(v);
    l = __float2bfloat16(v - __bfloat162float(h));
}

// ---------------- init (zero cnt + dtype flag) ----------------
__global__ void init_kernel() {
    int i = blockIdx.x * blockDim.x + threadIdx.x;
    if (i < NG) g_cnt[i] = 0;
    if (i == 0) g_is64 = 1;
}
__global__ void detect_kernel(const unsigned* __restrict__ w) {
    int i = blockIdx.x * blockDim.x + threadIdx.x;
    if (i < NE && w[2 * i + 1] != 0u) g_is64 = 0;
}

// ---------------- CSR construction ----------------
__device__ __forceinline__ int load_edge(const void* eiv, size_t pos) {
    if (g_is64) return (int)((const long long*)eiv)[pos];
    return ((const int*)eiv)[pos];
}
__global__ void count_kernel(const void* __restrict__ eiv) {
    int idx = blockIdx.x * blockDim.x + threadIdx.x;
    if (idx >= NE) return;
    int b = idx / E_;
    int e = idx - b * E_;
    int dst = load_edge(eiv, (size_t)b * 2 * E_ + E_ + e);
    atomicAdd(&g_cnt[b * N_ + dst], 1);
}
// Single-block scan over 80000 ints; also emits dinv = rsqrt(deg+1)
__global__ void scan_kernel() {
    __shared__ int part[1024];
    const int tid = threadIdx.x;
    const int CH  = (NG + 1023) / 1024;
    int start = tid * CH;
    int end   = start + CH; if (end > NG) end = NG;
    int s = 0;
    for (int i = start; i < end; i++) s += g_cnt[i];
    part[tid] = s;
    __syncthreads();
    for (int off = 1; off < 1024; off <<= 1) {
        int v = (tid >= off) ? part[tid - off] : 0;
        __syncthreads();
        part[tid] += v;
        __syncthreads();
    }
    int run = (tid > 0) ? part[tid - 1] : 0;
    for (int i = start; i < end; i++) {
        int c = g_cnt[i];
        g_off[i] = run;
        g_cur[i] = run;
        g_dinv[i] = rsqrtf((float)(c + 1));
        run += c;
    }
    if (tid == 1023) g_off[NG] = part[1023];
}
__global__ void fill_kernel(const void* __restrict__ eiv) {
    int idx = blockIdx.x * blockDim.x + threadIdx.x;
    if (idx >= NE) return;
    int b = idx / E_;
    int e = idx - b * E_;
    size_t base = (size_t)b * 2 * E_;
    int src = load_edge(eiv, base + e);
    int dst = load_edge(eiv, base + E_ + e);
    int pos = atomicAdd(&g_cur[b * N_ + dst], 1);
    g_esrc[pos] = b * N_ + src;
}

// ---------------- x0 split [hi(F) | lo(F)] per row -------------------------
__global__ void split_x0_kernel(const float* __restrict__ x0) {
    int i = blockIdx.x * blockDim.x + threadIdx.x;   // over NG*F/4
    if (i >= NG * F_ / 4) return;
    int row = i >> 5;                  // F/4 = 32 quads per row
    int col = (i & 31) * 4;
    float4 v = ((const float4*)x0)[i];
    __nv_bfloat16 h0, h1, h2, h3, l0, l1, l2, l3;
    split1(v.x, h0, l0); split1(v.y, h1, l1); split1(v.z, h2, l2); split1(v.w, h3, l3);
    uint2 hw = make_uint2(pack_bf2(h0, h1), pack_bf2(h2, h3));
    uint2 lw = make_uint2(pack_bf2(l0, l1), pack_bf2(l2, l3));
    size_t base = (size_t)row * (2 * F_) + col;
    *(uint2*)&g_x0p[base]      = hw;
    *(uint2*)&g_x0p[base + F_] = lw;
}

// ---------------- weight transpose + tripled split -------------------------
// B'[n][k'] where k' = [hi(K) | lo(K) | hi(K)], B'[n][k] = split(W[k][n])
__global__ void wsplit_kernel(const float* __restrict__ W, __nv_bfloat16* __restrict__ T,
                              int K, int Nn) {
    int i = blockIdx.x * blockDim.x + threadIdx.x;
    if (i >= K * Nn) return;
    int n = i / K, k = i - n * K;
    float v = W[(size_t)k * Nn + n];
    __nv_bfloat16 h, l;
    split1(v, h, l);
    size_t base = (size_t)n * (3 * K);
    T[base + k]         = h;
    T[base + K + k]     = l;
    T[base + 2 * K + k] = h;
}

// ---------------- aggregation gather (warp per destination node) -----------
// xres = relu(agg + bc) + x0  -> split [hi|lo]
__global__ __launch_bounds__(256) void gather_kernel(const float* __restrict__ x0,
                                                     const float* __restrict__ bc) {
    int warp = (blockIdx.x * blockDim.x + threadIdx.x) >> 5;
    int lane = threadIdx.x & 31;
    if (warp >= NG) return;

    const float4* xw4 = (const float4*)g_xw;
    float di = g_dinv[warp];

    float4 v  = xw4[(size_t)warp * 32 + lane];
    float  w0 = di * di;
    float4 acc;
    acc.x = w0 * v.x; acc.y = w0 * v.y; acc.z = w0 * v.z; acc.w = w0 * v.w;

    int e0 = g_off[warp], e1 = g_off[warp + 1];
    for (int e = e0; e < e1; e++) {
        int   s = g_esrc[e];
        float w = di * g_dinv[s];
        float4 u = xw4[(size_t)s * 32 + lane];
        acc.x += w * u.x; acc.y += w * u.y; acc.z += w * u.z; acc.w += w * u.w;
    }

    float4 b4 = ((const float4*)bc)[lane];
    float4 r4 = ((const float4*)x0)[(size_t)warp * 32 + lane];
    float o0 = fmaxf(acc.x + b4.x, 0.f) + r4.x;
    float o1 = fmaxf(acc.y + b4.y, 0.f) + r4.y;
    float o2 = fmaxf(acc.z + b4.z, 0.f) + r4.z;
    float o3 = fmaxf(acc.w + b4.w, 0.f) + r4.w;

    __nv_bfloat16 h0, h1, h2, h3, l0, l1, l2, l3;
    split1(o0, h0, l0); split1(o1, h1, l1); split1(o2, h2, l2); split1(o3, h3, l3);
    uint2 hw = make_uint2(pack_bf2(h0, h1), pack_bf2(h2, h3));
    uint2 lw = make_uint2(pack_bf2(l0, l1), pack_bf2(l2, l3));
    size_t base = (size_t)warp * (2 * F_) + lane * 4;
    *(uint2*)&g_xrp[base]      = hw;
    *(uint2*)&g_xrp[base + F_] = lw;
}

// ================= HMMA bf16 GEMM: k-chunk 64, 3-stage cp.async ============
// C[M,N] = act(A' @ B'^T + bias).
// A stored as [hi(Ka)|lo(Ka)] (row stride 2*Ka); logical K' = 3*Ka with
// section map {0,1,2} -> {hi, hi, lo}: srck = (k0 < Ka) ? k0 : k0 - Ka.
// B' stored tripled [hi|lo|hi] (row stride Kp = 3*Ka).
// CTA tile 128x128, 8 warps of 64x32. Smem row stride 144 B (9x16B, odd ->
// ldmatrix phase-conflict-free). 3 pipeline stages, dynamic smem.
// EPI: 0 = fp32 out (no bias/act); 1 = bias+leaky -> [hi|lo] bf16 out
//      (row stride 2*Nn); 2 = bias+leaky -> fp32 out.
#define ROWB_   144
#define A_BYTES_ (128 * ROWB_)      // 18432
#define STAGE_B_ (256 * ROWB_)      // 36864
#define SMEM_TOT_ (3 * STAGE_B_)    // 110592

template <int EPI>
__global__ __launch_bounds__(256) void gemm_bf16(
    const __nv_bfloat16* __restrict__ Ap, const __nv_bfloat16* __restrict__ Bp,
    const float* __restrict__ bias, float* __restrict__ Cf,
    __nv_bfloat16* __restrict__ Cbf, int Nn, int Ka)
{
    extern __shared__ __align__(16) char smem[];
    const int tid  = threadIdx.x;
    const int w    = tid >> 5;
    const int lane = tid & 31;
    const int m0 = blockIdx.y * 128;
    const int n0 = blockIdx.x * 128;
    const int m0w = (w >> 2) * 64;   // 2 warps in M
    const int n0w = (w & 3) * 32;    // 4 warps in N

    const uint32_t sb = smem_u32(smem);
    const int Kp = 3 * Ka;           // B row stride (tripled)
    const int As = 2 * Ka;           // A row stride (doubled)

    float acc[4][4][4];
#pragma unroll
    for (int a = 0; a < 4; a++)
#pragma unroll
        for (int b = 0; b < 4; b++)
#pragma unroll
            for (int q = 0; q < 4; q++) acc[a][b][q] = 0.f;

    // ldmatrix per-lane address selectors (stride 144 B)
    const int grp = lane >> 3, lr = lane & 7;
    const uint32_t aSel = (uint32_t)((m0w + (grp & 1) * 8 + lr) * ROWB_ + (grp >> 1) * 16);
    const uint32_t bSel = (uint32_t)((n0w + ((grp >> 1) & 1) * 8 + lr) * ROWB_ + (grp & 1) * 16);

    const int nk = Kp >> 6;          // 64-wide k-chunks

    // per-tile: 1024 16B chunks each for A and B; 4 of each per thread
#define PREFETCH(kc, st)                                                          \
    {                                                                             \
        const int k0_ = (kc) << 6;                                                \
        const int ak_ = (k0_ < Ka) ? k0_ : k0_ - Ka;                              \
        _Pragma("unroll")                                                         \
        for (int i_ = 0; i_ < 4; i_++) {                                          \
            int c_ = tid + i_ * 256;                                              \
            int row_ = c_ >> 3, q_ = (c_ & 7) * 8;                                \
            cp16(sb + (st) * STAGE_B_ + row_ * ROWB_ + q_ * 2,                    \
                 Ap + (size_t)(m0 + row_) * As + ak_ + q_);                       \
            cp16(sb + (st) * STAGE_B_ + A_BYTES_ + row_ * ROWB_ + q_ * 2,         \
                 Bp + (size_t)(n0 + row_) * Kp + k0_ + q_);                       \
        }                                                                         \
        cpcommit();                                                               \
    }

    PREFETCH(0, 0);
    PREFETCH(1, 1);

    for (int kc = 0; kc < nk; kc++) {
        const int st = kc % 3;
        if (kc + 2 < nk)      { const int s2 = (kc + 2) % 3; PREFETCH(kc + 2, s2); cpwait<2>(); }
        else if (kc + 1 < nk) { cpwait<1>(); }
        else                  { cpwait<0>(); }
        __syncthreads();

        const uint32_t aBase = sb + st * STAGE_B_ + aSel;
        const uint32_t bBase = sb + st * STAGE_B_ + A_BYTES_ + bSel;
#pragma unroll
        for (int ks = 0; ks < 4; ks++) {
            uint32_t a[4][4], b[2][4];
#pragma unroll
            for (int mi = 0; mi < 4; mi++)
                ldm4(a[mi], aBase + mi * 16 * ROWB_ + ks * 32);
#pragma unroll
            for (int nj = 0; nj < 2; nj++)
                ldm4(b[nj], bBase + nj * 16 * ROWB_ + ks * 32);
#pragma unroll
            for (int mi = 0; mi < 4; mi++)
#pragma unroll
                for (int nf = 0; nf < 4; nf++)
                    mma_bf16(acc[mi][nf], a[mi],
                             b[nf >> 1][(nf & 1) * 2], b[nf >> 1][(nf & 1) * 2 + 1]);
        }
        __syncthreads();   // protects stage st: re-filled next iteration
    }
#undef PREFETCH

    // ---- epilogue ----
    const int r0 = lane >> 2;
    const int cc = (lane & 3) * 2;
    const int rs = 2 * Nn;   // [hi|lo] row stride for EPI 1
#pragma unroll
    for (int mi = 0; mi < 4; mi++) {
        const int row1 = m0 + m0w + mi * 16 + r0;
        const int row2 = row1 + 8;
#pragma unroll
        for (int nf = 0; nf < 4; nf++) {
            const int col = n0 + n0w + nf * 8 + cc;
            float v0 = acc[mi][nf][0], v1 = acc[mi][nf][1];
            float v2 = acc[mi][nf][2], v3 = acc[mi][nf][3];
            if (EPI >= 1) {
                float bb0 = bias[col], bb1 = bias[col + 1];
                v0 += bb0; v1 += bb1; v2 += bb0; v3 += bb1;
                v0 = (v0 > 0.f) ? v0 : 0.01f * v0;
                v1 = (v1 > 0.f) ? v1 : 0.01f * v1;
                v2 = (v2 > 0.f) ? v2 : 0.01f * v2;
                v3 = (v3 > 0.f) ? v3 : 0.01f * v3;
            }
            if (EPI == 1) {
                __nv_bfloat16 h0, h1, h2, h3, l0, l1, l2, l3;
                split1(v0, h0, l0); split1(v1, h1, l1);
                split1(v2, h2, l2); split1(v3, h3, l3);
                size_t b1a = (size_t)row1 * rs + col;
                size_t b2a = (size_t)row2 * rs + col;
                *(uint32_t*)&Cbf[b1a]      = pack_bf2(h0, h1);
                *(uint32_t*)&Cbf[b1a + Nn] = pack_bf2(l0, l1);
                *(uint32_t*)&Cbf[b2a]      = pack_bf2(h2, h3);
                *(uint32_t*)&Cbf[b2a + Nn] = pack_bf2(l2, l3);
            } else {
                *(float2*)&Cf[(size_t)row1 * Nn + col] = make_float2(v0, v1);
                *(float2*)&Cf[(size_t)row2 * Nn + col] = make_float2(v2, v3);
            }
        }
    }
}

// ---------------- launch ----------------
extern "C" void kernel_launch(void* const* d_in, const int* in_sizes, int n_in,
                              void* d_out, int out_size) {
    const float* x0  = (const float*)d_in[0];   // [B,N,F]
    const void*  ei  = d_in[1];                 // [B,2,E] int32 OR int64
    const float* Wc  = (const float*)d_in[2];   // [F,F]
    const float* bc  = (const float*)d_in[3];   // [F]
    const float* W1  = (const float*)d_in[4];   // [F,H]
    const float* b1  = (const float*)d_in[5];   // [H]
    const float* W2  = (const float*)d_in[6];   // [H,H]
    const float* b2  = (const float*)d_in[7];   // [H]
    float*       out = (float*)d_out;           // [B,N,H]

    float* p_xw;
    __nv_bfloat16 *p_x0p, *p_xrp, *p_h1p, *p_wcp, *p_w1p, *p_w2p;
    cudaGetSymbolAddress((void**)&p_xw,  g_xw);
    cudaGetSymbolAddress((void**)&p_x0p, g_x0p);
    cudaGetSymbolAddress((void**)&p_xrp, g_xrp);
    cudaGetSymbolAddress((void**)&p_h1p, g_h1p);
    cudaGetSymbolAddress((void**)&p_wcp, g_wcp);
    cudaGetSymbolAddress((void**)&p_w1p, g_w1p);
    cudaGetSymbolAddress((void**)&p_w2p, g_w2p);

    cudaFuncSetAttribute(gemm_bf16<0>, cudaFuncAttributeMaxDynamicSharedMemorySize, SMEM_TOT_);
    cudaFuncSetAttribute(gemm_bf16<1>, cudaFuncAttributeMaxDynamicSharedMemorySize, SMEM_TOT_);
    cudaFuncSetAttribute(gemm_bf16<2>, cudaFuncAttributeMaxDynamicSharedMemorySize, SMEM_TOT_);

    // init + dtype probe
    init_kernel<<<(NG + 255) / 256, 256>>>();
    detect_kernel<<<(NE + 255) / 256, 256>>>((const unsigned*)ei);

    // CSR build
    count_kernel<<<(NE + 255) / 256, 256>>>(ei);
    scan_kernel<<<1, 1024>>>();
    fill_kernel<<<(NE + 255) / 256, 256>>>(ei);

    // operand prep
    split_x0_kernel<<<(NG * F_ / 4 + 255) / 256, 256>>>(x0);
    wsplit_kernel<<<(F_ * F_ + 255) / 256, 256>>>(Wc, p_wcp, F_, F_);
    wsplit_kernel<<<(F_ * H_ + 255) / 256, 256>>>(W1, p_w1p, F_, H_);
    wsplit_kernel<<<(H_ * H_ + 255) / 256, 256>>>(W2, p_w2p, H_, H_);

    // xw = x0 @ Wc   (fp32 out)  M=80000 N=128 K'=384
    {
        dim3 grid(F_ / 128, NG / 128);
        gemm_bf16<0><<<grid, 256, SMEM_TOT_>>>(p_x0p, p_wcp, nullptr, p_xw, nullptr, F_, F_);
    }

    // xres = relu(agg + bc) + x0 -> [hi|lo]
    gather_kernel<<<NG / 8, 256>>>(x0, bc);

    // h1 = leaky(xres @ W1 + b1) -> [hi|lo]   M=80000 N=256 K'=384
    {
        dim3 grid(H_ / 128, NG / 128);
        gemm_bf16<1><<<grid, 256, SMEM_TOT_>>>(p_xrp, p_w1p, b1, nullptr, p_h1p, H_, F_);
    }

    // out = leaky(h1 @ W2 + b2) -> fp32   M=80000 N=256 K'=768
    {
        dim3 grid(H_ / 128, NG / 128);
        gemm_bf16<2><<<grid, 256, SMEM_TOT_>>>(p_h1p, p_w2p, b2, out, nullptr, H_, H_);
    }
}

// round 12
// speedup vs baseline: 2.1617x; 1.4696x over previous
#include <cuda_runtime.h>
#include <cuda_bf16.h>
#include <cstdint>

// Problem dims (fixed by the dataset)
#define B_  8
#define N_  10000
#define E_  160000
#define F_  128
#define H_  256
#define NG  (B_ * N_)   // 80000 total nodes
#define NE  (B_ * E_)   // 1280000 total edges
#define SCAN_BLK 256
#define NBLK ((NG + SCAN_BLK - 1) / SCAN_BLK)   // 313

// ---------------- static scratch (no allocations allowed) ----------------
__device__ __align__(16) float          g_xw [NG * F_];       // x @ Wc (fp32, for gather)
__device__ __align__(16) __nv_bfloat16  g_x0p[NG * 2 * F_];   // x0 split [hi|lo]
__device__ __align__(16) __nv_bfloat16  g_xrp[NG * 2 * F_];   // xres split [hi|lo]
__device__ __align__(16) __nv_bfloat16  g_h1p[NG * 2 * H_];   // h1 split [hi|lo]
// weights transposed+split (tripled): B'[n][k'] with k' = [hi(K)|lo(K)|hi(K)]
__device__ __align__(16) __nv_bfloat16  g_wcp[F_ * 3 * F_];
__device__ __align__(16) __nv_bfloat16  g_w1p[H_ * 3 * F_];
__device__ __align__(16) __nv_bfloat16  g_w2p[H_ * 3 * H_];

__device__ int   g_cnt [NG];
__device__ float g_dinv[NG];
__device__ int   g_off [NG + 1];
__device__ int   g_cur [NG];
__device__ int   g_esrc[NE];
__device__ int   g_bsum[NBLK];
__device__ int   g_boff[NBLK];
__device__ int   g_is64;

// ================= helpers =================
__device__ __forceinline__ uint32_t smem_u32(const void* p) {
    uint32_t a;
    asm("{ .reg .u64 t; cvta.to.shared.u64 t, %1; cvt.u32.u64 %0, t; }" : "=r"(a) : "l"(p));
    return a;
}
__device__ __forceinline__ void cp16(uint32_t dst, const void* src) {
    asm volatile("cp.async.cg.shared.global [%0], [%1], 16;" :: "r"(dst), "l"(src) : "memory");
}
__device__ __forceinline__ void cpcommit() {
    asm volatile("cp.async.commit_group;" ::: "memory");
}
template <int Nw> __device__ __forceinline__ void cpwait() {
    asm volatile("cp.async.wait_group %0;" :: "n"(Nw) : "memory");
}
__device__ __forceinline__ void ldm4(uint32_t* r, uint32_t addr) {
    asm volatile("ldmatrix.sync.aligned.m8n8.x4.shared.b16 {%0,%1,%2,%3}, [%4];"
        : "=r"(r[0]), "=r"(r[1]), "=r"(r[2]), "=r"(r[3]) : "r"(addr));
}
__device__ __forceinline__ void mma_bf16(float* c, const uint32_t* a, uint32_t b0, uint32_t b1) {
    asm volatile(
        "mma.sync.aligned.m16n8k16.row.col.f32.bf16.bf16.f32 "
        "{%0,%1,%2,%3}, {%4,%5,%6,%7}, {%8,%9}, {%0,%1,%2,%3};"
        : "+f"(c[0]), "+f"(c[1]), "+f"(c[2]), "+f"(c[3])
        : "r"(a[0]), "r"(a[1]), "r"(a[2]), "r"(a[3]), "r"(b0), "r"(b1));
}
__device__ __forceinline__ uint32_t pack_bf2(__nv_bfloat16 a, __nv_bfloat16 b) {
    __nv_bfloat162 h2(a, b);
    return *reinterpret_cast<uint32_t*>(&h2);
}
__device__ __forceinline__ void split1(float v, __nv_bfloat16& h, __nv_bfloat16& l) {
    h = __float2bfloat16(v);
    l = __float2bfloat16(v - __bfloat162float(h));
}

// ---------------- init (zero cnt + dtype flag) ----------------
__global__ void init_kernel() {
    int i = blockIdx.x * blockDim.x + threadIdx.x;
    if (i < NG) g_cnt[i] = 0;
    if (i == 0) g_is64 = 1;
}
__global__ void detect_kernel(const unsigned* __restrict__ w) {
    int i = blockIdx.x * blockDim.x + threadIdx.x;
    if (i < NE && w[2 * i + 1] != 0u) g_is64 = 0;
}

// ---------------- CSR construction ----------------
__device__ __forceinline__ int load_edge(const void* eiv, size_t pos) {
    if (g_is64) return (int)((const long long*)eiv)[pos];
    return ((const int*)eiv)[pos];
}
__global__ void count_kernel(const void* __restrict__ eiv) {
    int idx = blockIdx.x * blockDim.x + threadIdx.x;
    if (idx >= NE) return;
    int b = idx / E_;
    int e = idx - b * E_;
    int dst = load_edge(eiv, (size_t)b * 2 * E_ + E_ + e);
    atomicAdd(&g_cnt[b * N_ + dst], 1);
}

// ---- 3-phase chip-wide scan ----
// scan1: per-block exclusive prefix into g_off (no block offset), block sum
//        into g_bsum, dinv fused.
__global__ __launch_bounds__(SCAN_BLK) void scan1_kernel() {
    __shared__ int sh[SCAN_BLK];
    int i = blockIdx.x * SCAN_BLK + threadIdx.x;
    int tid = threadIdx.x;
    int c = (i < NG) ? g_cnt[i] : 0;
    sh[tid] = c;
    __syncthreads();
    int pref = c;                       // inclusive
#pragma unroll
    for (int off = 1; off < SCAN_BLK; off <<= 1) {
        int v = (tid >= off) ? sh[tid - off] : 0;
        __syncthreads();
        pref += v;
        sh[tid] = pref;
        __syncthreads();
    }
    if (i < NG) {
        g_off[i]  = pref - c;           // exclusive within block
        g_dinv[i] = rsqrtf((float)(c + 1));
    }
    if (tid == SCAN_BLK - 1) g_bsum[blockIdx.x] = pref;
}
// scan2: single small block scans 313 block sums (exclusive) + total
__global__ __launch_bounds__(512) void scan2_kernel() {
    __shared__ int sh[512];
    int tid = threadIdx.x;
    int v = (tid < NBLK) ? g_bsum[tid] : 0;
    sh[tid] = v;
    __syncthreads();
    int pref = v;
#pragma unroll
    for (int off = 1; off < 512; off <<= 1) {
        int u = (tid >= off) ? sh[tid - off] : 0;
        __syncthreads();
        pref += u;
        sh[tid] = pref;
        __syncthreads();
    }
    if (tid < NBLK) g_boff[tid] = pref - v;
    if (tid == NBLK - 1) g_off[NG] = pref;
}
// scan3: add block offsets, materialize cursors
__global__ __launch_bounds__(SCAN_BLK) void scan3_kernel() {
    int i = blockIdx.x * SCAN_BLK + threadIdx.x;
    if (i >= NG) return;
    int o = g_off[i] + g_boff[blockIdx.x];
    g_off[i] = o;
    g_cur[i] = o;
}

__global__ void fill_kernel(const void* __restrict__ eiv) {
    int idx = blockIdx.x * blockDim.x + threadIdx.x;
    if (idx >= NE) return;
    int b = idx / E_;
    int e = idx - b * E_;
    size_t base = (size_t)b * 2 * E_;
    int src = load_edge(eiv, base + e);
    int dst = load_edge(eiv, base + E_ + e);
    int pos = atomicAdd(&g_cur[b * N_ + dst], 1);
    g_esrc[pos] = b * N_ + src;
}

// ---------------- x0 split [hi(F) | lo(F)] per row -------------------------
__global__ void split_x0_kernel(const float* __restrict__ x0) {
    int i = blockIdx.x * blockDim.x + threadIdx.x;   // over NG*F/4
    if (i >= NG * F_ / 4) return;
    int row = i >> 5;                  // F/4 = 32 quads per row
    int col = (i & 31) * 4;
    float4 v = ((const float4*)x0)[i];
    __nv_bfloat16 h0, h1, h2, h3, l0, l1, l2, l3;
    split1(v.x, h0, l0); split1(v.y, h1, l1); split1(v.z, h2, l2); split1(v.w, h3, l3);
    uint2 hw = make_uint2(pack_bf2(h0, h1), pack_bf2(h2, h3));
    uint2 lw = make_uint2(pack_bf2(l0, l1), pack_bf2(l2, l3));
    size_t base = (size_t)row * (2 * F_) + col;
    *(uint2*)&g_x0p[base]      = hw;
    *(uint2*)&g_x0p[base + F_] = lw;
}

// ---------------- weight transpose + tripled split -------------------------
// B'[n][k'] where k' = [hi(K) | lo(K) | hi(K)], B'[n][k] = split(W[k][n])
__global__ void wsplit_kernel(const float* __restrict__ W, __nv_bfloat16* __restrict__ T,
                              int K, int Nn) {
    int i = blockIdx.x * blockDim.x + threadIdx.x;
    if (i >= K * Nn) return;
    int n = i / K, k = i - n * K;
    float v = W[(size_t)k * Nn + n];
    __nv_bfloat16 h, l;
    split1(v, h, l);
    size_t base = (size_t)n * (3 * K);
    T[base + k]         = h;
    T[base + K + k]     = l;
    T[base + 2 * K + k] = h;
}

// ---------------- aggregation gather (warp per destination node) -----------
// xres = relu(agg + bc) + x0  -> split [hi|lo]
__global__ __launch_bounds__(256) void gather_kernel(const float* __restrict__ x0,
                                                     const float* __restrict__ bc) {
    int warp = (blockIdx.x * blockDim.x + threadIdx.x) >> 5;
    int lane = threadIdx.x & 31;
    if (warp >= NG) return;

    const float4* xw4 = (const float4*)g_xw;
    float di = g_dinv[warp];

    float4 v  = xw4[(size_t)warp * 32 + lane];
    float  w0 = di * di;
    float4 acc;
    acc.x = w0 * v.x; acc.y = w0 * v.y; acc.z = w0 * v.z; acc.w = w0 * v.w;

    int e0 = g_off[warp], e1 = g_off[warp + 1];
    for (int e = e0; e < e1; e++) {
        int   s = g_esrc[e];
        float w = di * g_dinv[s];
        float4 u = xw4[(size_t)s * 32 + lane];
        acc.x += w * u.x; acc.y += w * u.y; acc.z += w * u.z; acc.w += w * u.w;
    }

    float4 b4 = ((const float4*)bc)[lane];
    float4 r4 = ((const float4*)x0)[(size_t)warp * 32 + lane];
    float o0 = fmaxf(acc.x + b4.x, 0.f) + r4.x;
    float o1 = fmaxf(acc.y + b4.y, 0.f) + r4.y;
    float o2 = fmaxf(acc.z + b4.z, 0.f) + r4.z;
    float o3 = fmaxf(acc.w + b4.w, 0.f) + r4.w;

    __nv_bfloat16 h0, h1, h2, h3, l0, l1, l2, l3;
    split1(o0, h0, l0); split1(o1, h1, l1); split1(o2, h2, l2); split1(o3, h3, l3);
    uint2 hw = make_uint2(pack_bf2(h0, h1), pack_bf2(h2, h3));
    uint2 lw = make_uint2(pack_bf2(l0, l1), pack_bf2(l2, l3));
    size_t base = (size_t)warp * (2 * F_) + lane * 4;
    *(uint2*)&g_xrp[base]      = hw;
    *(uint2*)&g_xrp[base + F_] = lw;
}

// ================= HMMA bf16 GEMM: k-chunk 64, 3-stage cp.async ============
// C[M,N] = act(A' @ B'^T + bias).
// A stored as [hi(Ka)|lo(Ka)] (row stride 2*Ka); logical K' = 3*Ka with
// section map {0,1,2} -> {hi, hi, lo}: srck = (k0 < Ka) ? k0 : k0 - Ka.
// B' stored tripled [hi|lo|hi] (row stride Kp = 3*Ka).
// CTA tile 128x128, 8 warps of 64x32. Smem row stride 144 B (9x16B, odd ->
// ldmatrix phase-conflict-free). 3 pipeline stages, dynamic smem.
// EPI: 0 = fp32 out (no bias/act); 1 = bias+leaky -> [hi|lo] bf16 out
//      (row stride 2*Nn); 2 = bias+leaky -> fp32 out.
#define ROWB_   144
#define A_BYTES_ (128 * ROWB_)      // 18432
#define STAGE_B_ (256 * ROWB_)      // 36864
#define SMEM_TOT_ (3 * STAGE_B_)    // 110592

template <int EPI>
__global__ __launch_bounds__(256) void gemm_bf16(
    const __nv_bfloat16* __restrict__ Ap, const __nv_bfloat16* __restrict__ Bp,
    const float* __restrict__ bias, float* __restrict__ Cf,
    __nv_bfloat16* __restrict__ Cbf, int Nn, int Ka)
{
    extern __shared__ __align__(16) char smem[];
    const int tid  = threadIdx.x;
    const int w    = tid >> 5;
    const int lane = tid & 31;
    const int m0 = blockIdx.y * 128;
    const int n0 = blockIdx.x * 128;
    const int m0w = (w >> 2) * 64;   // 2 warps in M
    const int n0w = (w & 3) * 32;    // 4 warps in N

    const uint32_t sb = smem_u32(smem);
    const int Kp = 3 * Ka;           // B row stride (tripled)
    const int As = 2 * Ka;           // A row stride (doubled)

    float acc[4][4][4];
#pragma unroll
    for (int a = 0; a < 4; a++)
#pragma unroll
        for (int b = 0; b < 4; b++)
#pragma unroll
            for (int q = 0; q < 4; q++) acc[a][b][q] = 0.f;

    // ldmatrix per-lane address selectors (stride 144 B)
    const int grp = lane >> 3, lr = lane & 7;
    const uint32_t aSel = (uint32_t)((m0w + (grp & 1) * 8 + lr) * ROWB_ + (grp >> 1) * 16);
    const uint32_t bSel = (uint32_t)((n0w + ((grp >> 1) & 1) * 8 + lr) * ROWB_ + (grp & 1) * 16);

    const int nk = Kp >> 6;          // 64-wide k-chunks

    // per-tile: 1024 16B chunks each for A and B; 4 of each per thread
#define PREFETCH(kc, st)                                                          \
    {                                                                             \
        const int k0_ = (kc) << 6;                                                \
        const int ak_ = (k0_ < Ka) ? k0_ : k0_ - Ka;                              \
        _Pragma("unroll")                                                         \
        for (int i_ = 0; i_ < 4; i_++) {                                          \
            int c_ = tid + i_ * 256;                                              \
            int row_ = c_ >> 3, q_ = (c_ & 7) * 8;                                \
            cp16(sb + (st) * STAGE_B_ + row_ * ROWB_ + q_ * 2,                    \
                 Ap + (size_t)(m0 + row_) * As + ak_ + q_);                       \
            cp16(sb + (st) * STAGE_B_ + A_BYTES_ + row_ * ROWB_ + q_ * 2,         \
                 Bp + (size_t)(n0 + row_) * Kp + k0_ + q_);                       \
        }                                                                         \
        cpcommit();                                                               \
    }

    PREFETCH(0, 0);
    PREFETCH(1, 1);

    for (int kc = 0; kc < nk; kc++) {
        const int st = kc % 3;
        if (kc + 2 < nk)      { const int s2 = (kc + 2) % 3; PREFETCH(kc + 2, s2); cpwait<2>(); }
        else if (kc + 1 < nk) { cpwait<1>(); }
        else                  { cpwait<0>(); }
        __syncthreads();

        const uint32_t aBase = sb + st * STAGE_B_ + aSel;
        const uint32_t bBase = sb + st * STAGE_B_ + A_BYTES_ + bSel;
#pragma unroll
        for (int ks = 0; ks < 4; ks++) {
            uint32_t a[4][4], b[2][4];
#pragma unroll
            for (int mi = 0; mi < 4; mi++)
                ldm4(a[mi], aBase + mi * 16 * ROWB_ + ks * 32);
#pragma unroll
            for (int nj = 0; nj < 2; nj++)
                ldm4(b[nj], bBase + nj * 16 * ROWB_ + ks * 32);
#pragma unroll
            for (int mi = 0; mi < 4; mi++)
#pragma unroll
                for (int nf = 0; nf < 4; nf++)
                    mma_bf16(acc[mi][nf], a[mi],
                             b[nf >> 1][(nf & 1) * 2], b[nf >> 1][(nf & 1) * 2 + 1]);
        }
        __syncthreads();   // protects stage st: re-filled next iteration
    }
#undef PREFETCH

    // ---- epilogue ----
    const int r0 = lane >> 2;
    const int cc = (lane & 3) * 2;
    const int rs = 2 * Nn;   // [hi|lo] row stride for EPI 1
#pragma unroll
    for (int mi = 0; mi < 4; mi++) {
        const int row1 = m0 + m0w + mi * 16 + r0;
        const int row2 = row1 + 8;
#pragma unroll
        for (int nf = 0; nf < 4; nf++) {
            const int col = n0 + n0w + nf * 8 + cc;
            float v0 = acc[mi][nf][0], v1 = acc[mi][nf][1];
            float v2 = acc[mi][nf][2], v3 = acc[mi][nf][3];
            if (EPI >= 1) {
                float bb0 = bias[col], bb1 = bias[col + 1];
                v0 += bb0; v1 += bb1; v2 += bb0; v3 += bb1;
                v0 = (v0 > 0.f) ? v0 : 0.01f * v0;
                v1 = (v1 > 0.f) ? v1 : 0.01f * v1;
                v2 = (v2 > 0.f) ? v2 : 0.01f * v2;
                v3 = (v3 > 0.f) ? v3 : 0.01f * v3;
            }
            if (EPI == 1) {
                __nv_bfloat16 h0, h1, h2, h3, l0, l1, l2, l3;
                split1(v0, h0, l0); split1(v1, h1, l1);
                split1(v2, h2, l2); split1(v3, h3, l3);
                size_t b1a = (size_t)row1 * rs + col;
                size_t b2a = (size_t)row2 * rs + col;
                *(uint32_t*)&Cbf[b1a]      = pack_bf2(h0, h1);
                *(uint32_t*)&Cbf[b1a + Nn] = pack_bf2(l0, l1);
                *(uint32_t*)&Cbf[b2a]      = pack_bf2(h2, h3);
                *(uint32_t*)&Cbf[b2a + Nn] = pack_bf2(l2, l3);
            } else {
                *(float2*)&Cf[(size_t)row1 * Nn + col] = make_float2(v0, v1);
                *(float2*)&Cf[(size_t)row2 * Nn + col] = make_float2(v2, v3);
            }
        }
    }
}

// ---------------- launch ----------------
extern "C" void kernel_launch(void* const* d_in, const int* in_sizes, int n_in,
                              void* d_out, int out_size) {
    const float* x0  = (const float*)d_in[0];   // [B,N,F]
    const void*  ei  = d_in[1];                 // [B,2,E] int32 OR int64
    const float* Wc  = (const float*)d_in[2];   // [F,F]
    const float* bc  = (const float*)d_in[3];   // [F]
    const float* W1  = (const float*)d_in[4];   // [F,H]
    const float* b1  = (const float*)d_in[5];   // [H]
    const float* W2  = (const float*)d_in[6];   // [H,H]
    const float* b2  = (const float*)d_in[7];   // [H]
    float*       out = (float*)d_out;           // [B,N,H]

    float* p_xw;
    __nv_bfloat16 *p_x0p, *p_xrp, *p_h1p, *p_wcp, *p_w1p, *p_w2p;
    cudaGetSymbolAddress((void**)&p_xw,  g_xw);
    cudaGetSymbolAddress((void**)&p_x0p, g_x0p);
    cudaGetSymbolAddress((void**)&p_xrp, g_xrp);
    cudaGetSymbolAddress((void**)&p_h1p, g_h1p);
    cudaGetSymbolAddress((void**)&p_wcp, g_wcp);
    cudaGetSymbolAddress((void**)&p_w1p, g_w1p);
    cudaGetSymbolAddress((void**)&p_w2p, g_w2p);

    cudaFuncSetAttribute(gemm_bf16<0>, cudaFuncAttributeMaxDynamicSharedMemorySize, SMEM_TOT_);
    cudaFuncSetAttribute(gemm_bf16<1>, cudaFuncAttributeMaxDynamicSharedMemorySize, SMEM_TOT_);
    cudaFuncSetAttribute(gemm_bf16<2>, cudaFuncAttributeMaxDynamicSharedMemorySize, SMEM_TOT_);

    // init + dtype probe
    init_kernel<<<(NG + 255) / 256, 256>>>();
    detect_kernel<<<(NE + 255) / 256, 256>>>((const unsigned*)ei);

    // CSR build (chip-wide 3-phase scan)
    count_kernel<<<(NE + 255) / 256, 256>>>(ei);
    scan1_kernel<<<NBLK, SCAN_BLK>>>();
    scan2_kernel<<<1, 512>>>();
    scan3_kernel<<<NBLK, SCAN_BLK>>>();
    fill_kernel<<<(NE + 255) / 256, 256>>>(ei);

    // operand prep
    split_x0_kernel<<<(NG * F_ / 4 + 255) / 256, 256>>>(x0);
    wsplit_kernel<<<(F_ * F_ + 255) / 256, 256>>>(Wc, p_wcp, F_, F_);
    wsplit_kernel<<<(F_ * H_ + 255) / 256, 256>>>(W1, p_w1p, F_, H_);
    wsplit_kernel<<<(H_ * H_ + 255) / 256, 256>>>(W2, p_w2p, H_, H_);

    // xw = x0 @ Wc   (fp32 out)  M=80000 N=128 K'=384
    {
        dim3 grid(F_ / 128, NG / 128);
        gemm_bf16<0><<<grid, 256, SMEM_TOT_>>>(p_x0p, p_wcp, nullptr, p_xw, nullptr, F_, F_);
    }

    // xres = relu(agg + bc) + x0 -> [hi|lo]
    gather_kernel<<<NG / 8, 256>>>(x0, bc);

    // h1 = leaky(xres @ W1 + b1) -> [hi|lo]   M=80000 N=256 K'=384
    {
        dim3 grid(H_ / 128, NG / 128);
        gemm_bf16<1><<<grid, 256, SMEM_TOT_>>>(p_xrp, p_w1p, b1, nullptr, p_h1p, H_, F_);
    }

    // out = leaky(h1 @ W2 + b2) -> fp32   M=80000 N=256 K'=768
    {
        dim3 grid(H_ / 128, NG / 128);
        gemm_bf16<2><<<grid, 256, SMEM_TOT_>>>(p_h1p, p_w2p, b2, out, nullptr, H_, H_);
    }
}

// round 13
// speedup vs baseline: 2.2897x; 1.0592x over previous
#include <cuda_runtime.h>
#include <cuda_bf16.h>
#include <cstdint>

// Problem dims (fixed by the dataset)
#define B_  8
#define N_  10000
#define E_  160000
#define F_  128
#define H_  256
#define NG  (B_ * N_)   // 80000 total nodes
#define NE  (B_ * E_)   // 1280000 total edges
#define SCAN_BLK 256
#define NBLK ((NG + SCAN_BLK - 1) / SCAN_BLK)   // 313

// ---------------- static scratch (no allocations allowed) ----------------
__device__ __align__(16) float          g_xw [NG * F_];       // x @ Wc (fp32, for gather)
__device__ __align__(16) __nv_bfloat16  g_x0p[NG * 2 * F_];   // x0 split [hi|lo]
__device__ __align__(16) __nv_bfloat16  g_xrp[NG * 2 * F_];   // xres split [hi|lo]
__device__ __align__(16) __nv_bfloat16  g_h1p[NG * 2 * H_];   // h1 split [hi|lo]
// weights transposed+split (tripled): B'[n][k'] with k' = [hi(K)|lo(K)|hi(K)]
__device__ __align__(16) __nv_bfloat16  g_wcp[F_ * 3 * F_];
__device__ __align__(16) __nv_bfloat16  g_w1p[H_ * 3 * F_];
__device__ __align__(16) __nv_bfloat16  g_w2p[H_ * 3 * H_];

__device__ int   g_cnt [NG];
__device__ float g_dinv[NG];
__device__ int   g_off [NG + 1];
__device__ int   g_cur [NG];
__device__ int   g_esrc[NE];
__device__ int   g_bsum[NBLK];
__device__ int   g_boff[NBLK];
__device__ int   g_is64;

// ================= helpers =================
__device__ __forceinline__ uint32_t smem_u32(const void* p) {
    uint32_t a;
    asm("{ .reg .u64 t; cvta.to.shared.u64 t, %1; cvt.u32.u64 %0, t; }" : "=r"(a) : "l"(p));
    return a;
}
__device__ __forceinline__ void cp16(uint32_t dst, const void* src) {
    asm volatile("cp.async.cg.shared.global [%0], [%1], 16;" :: "r"(dst), "l"(src) : "memory");
}
__device__ __forceinline__ void cpcommit() {
    asm volatile("cp.async.commit_group;" ::: "memory");
}
template <int Nw> __device__ __forceinline__ void cpwait() {
    asm volatile("cp.async.wait_group %0;" :: "n"(Nw) : "memory");
}
__device__ __forceinline__ void ldm4(uint32_t* r, uint32_t addr) {
    asm volatile("ldmatrix.sync.aligned.m8n8.x4.shared.b16 {%0,%1,%2,%3}, [%4];"
        : "=r"(r[0]), "=r"(r[1]), "=r"(r[2]), "=r"(r[3]) : "r"(addr));
}
__device__ __forceinline__ void mma_bf16(float* c, const uint32_t* a, uint32_t b0, uint32_t b1) {
    asm volatile(
        "mma.sync.aligned.m16n8k16.row.col.f32.bf16.bf16.f32 "
        "{%0,%1,%2,%3}, {%4,%5,%6,%7}, {%8,%9}, {%0,%1,%2,%3};"
        : "+f"(c[0]), "+f"(c[1]), "+f"(c[2]), "+f"(c[3])
        : "r"(a[0]), "r"(a[1]), "r"(a[2]), "r"(a[3]), "r"(b0), "r"(b1));
}
__device__ __forceinline__ uint32_t pack_bf2(__nv_bfloat16 a, __nv_bfloat16 b) {
    __nv_bfloat162 h2(a, b);
    return *reinterpret_cast<uint32_t*>(&h2);
}
__device__ __forceinline__ void split1(float v, __nv_bfloat16& h, __nv_bfloat16& l) {
    h = __float2bfloat16(v);
    l = __float2bfloat16(v - __bfloat162float(h));
}

// ---------------- init (zero cnt + dtype flag) ----------------
__global__ void init_kernel() {
    int i = blockIdx.x * blockDim.x + threadIdx.x;
    if (i < NG) g_cnt[i] = 0;
    if (i == 0) g_is64 = 1;
}
__global__ void detect_kernel(const unsigned* __restrict__ w) {
    int i = blockIdx.x * blockDim.x + threadIdx.x;
    if (i < NE && w[2 * i + 1] != 0u) g_is64 = 0;
}

// ---------------- CSR construction ----------------
__device__ __forceinline__ int load_edge(const void* eiv, size_t pos) {
    if (g_is64) return (int)((const long long*)eiv)[pos];
    return ((const int*)eiv)[pos];
}
__global__ void count_kernel(const void* __restrict__ eiv) {
    int idx = blockIdx.x * blockDim.x + threadIdx.x;
    if (idx >= NE) return;
    int b = idx / E_;
    int e = idx - b * E_;
    int dst = load_edge(eiv, (size_t)b * 2 * E_ + E_ + e);
    atomicAdd(&g_cnt[b * N_ + dst], 1);
}

// ---- 3-phase chip-wide scan ----
__global__ __launch_bounds__(SCAN_BLK) void scan1_kernel() {
    __shared__ int sh[SCAN_BLK];
    int i = blockIdx.x * SCAN_BLK + threadIdx.x;
    int tid = threadIdx.x;
    int c = (i < NG) ? g_cnt[i] : 0;
    sh[tid] = c;
    __syncthreads();
    int pref = c;
#pragma unroll
    for (int off = 1; off < SCAN_BLK; off <<= 1) {
        int v = (tid >= off) ? sh[tid - off] : 0;
        __syncthreads();
        pref += v;
        sh[tid] = pref;
        __syncthreads();
    }
    if (i < NG) {
        g_off[i]  = pref - c;
        g_dinv[i] = rsqrtf((float)(c + 1));
    }
    if (tid == SCAN_BLK - 1) g_bsum[blockIdx.x] = pref;
}
__global__ __launch_bounds__(512) void scan2_kernel() {
    __shared__ int sh[512];
    int tid = threadIdx.x;
    int v = (tid < NBLK) ? g_bsum[tid] : 0;
    sh[tid] = v;
    __syncthreads();
    int pref = v;
#pragma unroll
    for (int off = 1; off < 512; off <<= 1) {
        int u = (tid >= off) ? sh[tid - off] : 0;
        __syncthreads();
        pref += u;
        sh[tid] = pref;
        __syncthreads();
    }
    if (tid < NBLK) g_boff[tid] = pref - v;
    if (tid == NBLK - 1) g_off[NG] = pref;
}
__global__ __launch_bounds__(SCAN_BLK) void scan3_kernel() {
    int i = blockIdx.x * SCAN_BLK + threadIdx.x;
    if (i >= NG) return;
    int o = g_off[i] + g_boff[blockIdx.x];
    g_off[i] = o;
    g_cur[i] = o;
}

__global__ void fill_kernel(const void* __restrict__ eiv) {
    int idx = blockIdx.x * blockDim.x + threadIdx.x;
    if (idx >= NE) return;
    int b = idx / E_;
    int e = idx - b * E_;
    size_t base = (size_t)b * 2 * E_;
    int src = load_edge(eiv, base + e);
    int dst = load_edge(eiv, base + E_ + e);
    int pos = atomicAdd(&g_cur[b * N_ + dst], 1);
    g_esrc[pos] = b * N_ + src;
}

// ---------------- x0 split [hi(F) | lo(F)] per row -------------------------
__global__ void split_x0_kernel(const float* __restrict__ x0) {
    int i = blockIdx.x * blockDim.x + threadIdx.x;   // over NG*F/4
    if (i >= NG * F_ / 4) return;
    int row = i >> 5;
    int col = (i & 31) * 4;
    float4 v = ((const float4*)x0)[i];
    __nv_bfloat16 h0, h1, h2, h3, l0, l1, l2, l3;
    split1(v.x, h0, l0); split1(v.y, h1, l1); split1(v.z, h2, l2); split1(v.w, h3, l3);
    uint2 hw = make_uint2(pack_bf2(h0, h1), pack_bf2(h2, h3));
    uint2 lw = make_uint2(pack_bf2(l0, l1), pack_bf2(l2, l3));
    size_t base = (size_t)row * (2 * F_) + col;
    *(uint2*)&g_x0p[base]      = hw;
    *(uint2*)&g_x0p[base + F_] = lw;
}

// ---------------- all three weight transposes+splits in ONE kernel ---------
// segment 0: Wc (K=F,N=F)  -> g_wcp ; 1: W1 (K=F,N=H) -> g_w1p ;
// segment 2: W2 (K=H,N=H)  -> g_w2p.  B'[n][k'] = [hi(K)|lo(K)|hi(K)].
__global__ void wsplit_all_kernel(const float* __restrict__ Wc,
                                  const float* __restrict__ W1,
                                  const float* __restrict__ W2) {
    int i = blockIdx.x * blockDim.x + threadIdx.x;
    const int n0 = F_ * F_;          // 16384
    const int n1 = F_ * H_;          // 32768
    const int n2 = H_ * H_;          // 65536
    const float* W; __nv_bfloat16* T; int K, idx;
    if (i < n0)                { W = Wc; T = g_wcp; K = F_; idx = i; }
    else if (i < n0 + n1)      { W = W1; T = g_w1p; K = F_; idx = i - n0; }
    else if (i < n0 + n1 + n2) { W = W2; T = g_w2p; K = H_; idx = i - n0 - n1; }
    else return;
    int Nn = (T == g_wcp) ? F_ : H_;
    int n = idx / K, k = idx - n * K;
    float v = W[(size_t)k * Nn + n];
    __nv_bfloat16 h, l;
    split1(v, h, l);
    size_t base = (size_t)n * (3 * K);
    T[base + k]         = h;
    T[base + K + k]     = l;
    T[base + 2 * K + k] = h;
}

// ---------------- aggregation gather (warp per destination node) -----------
__global__ __launch_bounds__(256) void gather_kernel(const float* __restrict__ x0,
                                                     const float* __restrict__ bc) {
    int warp = (blockIdx.x * blockDim.x + threadIdx.x) >> 5;
    int lane = threadIdx.x & 31;
    if (warp >= NG) return;

    const float4* xw4 = (const float4*)g_xw;
    float di = g_dinv[warp];

    float4 v  = xw4[(size_t)warp * 32 + lane];
    float  w0 = di * di;
    float4 acc;
    acc.x = w0 * v.x; acc.y = w0 * v.y; acc.z = w0 * v.z; acc.w = w0 * v.w;

    int e0 = g_off[warp], e1 = g_off[warp + 1];
    for (int e = e0; e < e1; e++) {
        int   s = g_esrc[e];
        float w = di * g_dinv[s];
        float4 u = xw4[(size_t)s * 32 + lane];
        acc.x += w * u.x; acc.y += w * u.y; acc.z += w * u.z; acc.w += w * u.w;
    }

    float4 b4 = ((const float4*)bc)[lane];
    float4 r4 = ((const float4*)x0)[(size_t)warp * 32 + lane];
    float o0 = fmaxf(acc.x + b4.x, 0.f) + r4.x;
    float o1 = fmaxf(acc.y + b4.y, 0.f) + r4.y;
    float o2 = fmaxf(acc.z + b4.z, 0.f) + r4.z;
    float o3 = fmaxf(acc.w + b4.w, 0.f) + r4.w;

    __nv_bfloat16 h0, h1, h2, h3, l0, l1, l2, l3;
    split1(o0, h0, l0); split1(o1, h1, l1); split1(o2, h2, l2); split1(o3, h3, l3);
    uint2 hw = make_uint2(pack_bf2(h0, h1), pack_bf2(h2, h3));
    uint2 lw = make_uint2(pack_bf2(l0, l1), pack_bf2(l2, l3));
    size_t base = (size_t)warp * (2 * F_) + lane * 4;
    *(uint2*)&g_xrp[base]      = hw;
    *(uint2*)&g_xrp[base + F_] = lw;
}

// ================= HMMA bf16 GEMM: k-chunk 64, 3-stage cp.async ============
#define ROWB_   144
#define A_BYTES_ (128 * ROWB_)      // 18432
#define STAGE_B_ (256 * ROWB_)      // 36864
#define SMEM_TOT_ (3 * STAGE_B_)    // 110592

template <int EPI>
__global__ __launch_bounds__(256) void gemm_bf16(
    const __nv_bfloat16* __restrict__ Ap, const __nv_bfloat16* __restrict__ Bp,
    const float* __restrict__ bias, float* __restrict__ Cf,
    __nv_bfloat16* __restrict__ Cbf, int Nn, int Ka)
{
    extern __shared__ __align__(16) char smem[];
    const int tid  = threadIdx.x;
    const int w    = tid >> 5;
    const int lane = tid & 31;
    const int m0 = blockIdx.y * 128;
    const int n0 = blockIdx.x * 128;
    const int m0w = (w >> 2) * 64;
    const int n0w = (w & 3) * 32;

    const uint32_t sb = smem_u32(smem);
    const int Kp = 3 * Ka;
    const int As = 2 * Ka;

    float acc[4][4][4];
#pragma unroll
    for (int a = 0; a < 4; a++)
#pragma unroll
        for (int b = 0; b < 4; b++)
#pragma unroll
            for (int q = 0; q < 4; q++) acc[a][b][q] = 0.f;

    const int grp = lane >> 3, lr = lane & 7;
    const uint32_t aSel = (uint32_t)((m0w + (grp & 1) * 8 + lr) * ROWB_ + (grp >> 1) * 16);
    const uint32_t bSel = (uint32_t)((n0w + ((grp >> 1) & 1) * 8 + lr) * ROWB_ + (grp & 1) * 16);

    const int nk = Kp >> 6;

#define PREFETCH(kc, st)                                                          \
    {                                                                             \
        const int k0_ = (kc) << 6;                                                \
        const int ak_ = (k0_ < Ka) ? k0_ : k0_ - Ka;                              \
        _Pragma("unroll")                                                         \
        for (int i_ = 0; i_ < 4; i_++) {                                          \
            int c_ = tid + i_ * 256;                                              \
            int row_ = c_ >> 3, q_ = (c_ & 7) * 8;                                \
            cp16(sb + (st) * STAGE_B_ + row_ * ROWB_ + q_ * 2,                    \
                 Ap + (size_t)(m0 + row_) * As + ak_ + q_);                       \
            cp16(sb + (st) * STAGE_B_ + A_BYTES_ + row_ * ROWB_ + q_ * 2,         \
                 Bp + (size_t)(n0 + row_) * Kp + k0_ + q_);                       \
        }                                                                         \
        cpcommit();                                                               \
    }

    PREFETCH(0, 0);
    PREFETCH(1, 1);

    for (int kc = 0; kc < nk; kc++) {
        const int st = kc % 3;
        if (kc + 2 < nk)      { const int s2 = (kc + 2) % 3; PREFETCH(kc + 2, s2); cpwait<2>(); }
        else if (kc + 1 < nk) { cpwait<1>(); }
        else                  { cpwait<0>(); }
        __syncthreads();

        const uint32_t aBase = sb + st * STAGE_B_ + aSel;
        const uint32_t bBase = sb + st * STAGE_B_ + A_BYTES_ + bSel;
#pragma unroll
        for (int ks = 0; ks < 4; ks++) {
            uint32_t a[4][4], b[2][4];
#pragma unroll
            for (int mi = 0; mi < 4; mi++)
                ldm4(a[mi], aBase + mi * 16 * ROWB_ + ks * 32);
#pragma unroll
            for (int nj = 0; nj < 2; nj++)
                ldm4(b[nj], bBase + nj * 16 * ROWB_ + ks * 32);
#pragma unroll
            for (int mi = 0; mi < 4; mi++)
#pragma unroll
                for (int nf = 0; nf < 4; nf++)
                    mma_bf16(acc[mi][nf], a[mi],
                             b[nf >> 1][(nf & 1) * 2], b[nf >> 1][(nf & 1) * 2 + 1]);
        }
        __syncthreads();
    }
#undef PREFETCH

    const int r0 = lane >> 2;
    const int cc = (lane & 3) * 2;
    const int rs = 2 * Nn;
#pragma unroll
    for (int mi = 0; mi < 4; mi++) {
        const int row1 = m0 + m0w + mi * 16 + r0;
        const int row2 = row1 + 8;
#pragma unroll
        for (int nf = 0; nf < 4; nf++) {
            const int col = n0 + n0w + nf * 8 + cc;
            float v0 = acc[mi][nf][0], v1 = acc[mi][nf][1];
            float v2 = acc[mi][nf][2], v3 = acc[mi][nf][3];
            if (EPI >= 1) {
                float bb0 = bias[col], bb1 = bias[col + 1];
                v0 += bb0; v1 += bb1; v2 += bb0; v3 += bb1;
                v0 = (v0 > 0.f) ? v0 : 0.01f * v0;
                v1 = (v1 > 0.f) ? v1 : 0.01f * v1;
                v2 = (v2 > 0.f) ? v2 : 0.01f * v2;
                v3 = (v3 > 0.f) ? v3 : 0.01f * v3;
            }
            if (EPI == 1) {
                __nv_bfloat16 h0, h1, h2, h3, l0, l1, l2, l3;
                split1(v0, h0, l0); split1(v1, h1, l1);
                split1(v2, h2, l2); split1(v3, h3, l3);
                size_t b1a = (size_t)row1 * rs + col;
                size_t b2a = (size_t)row2 * rs + col;
                *(uint32_t*)&Cbf[b1a]      = pack_bf2(h0, h1);
                *(uint32_t*)&Cbf[b1a + Nn] = pack_bf2(l0, l1);
                *(uint32_t*)&Cbf[b2a]      = pack_bf2(h2, h3);
                *(uint32_t*)&Cbf[b2a + Nn] = pack_bf2(l2, l3);
            } else {
                *(float2*)&Cf[(size_t)row1 * Nn + col] = make_float2(v0, v1);
                *(float2*)&Cf[(size_t)row2 * Nn + col] = make_float2(v2, v3);
            }
        }
    }
}

// ---------------- launch ----------------
extern "C" void kernel_launch(void* const* d_in, const int* in_sizes, int n_in,
                              void* d_out, int out_size) {
    const float* x0  = (const float*)d_in[0];   // [B,N,F]
    const void*  ei  = d_in[1];                 // [B,2,E] int32 OR int64
    const float* Wc  = (const float*)d_in[2];   // [F,F]
    const float* bc  = (const float*)d_in[3];   // [F]
    const float* W1  = (const float*)d_in[4];   // [F,H]
    const float* b1  = (const float*)d_in[5];   // [H]
    const float* W2  = (const float*)d_in[6];   // [H,H]
    const float* b2  = (const float*)d_in[7];   // [H]
    float*       out = (float*)d_out;           // [B,N,H]

    float* p_xw;
    __nv_bfloat16 *p_x0p, *p_xrp, *p_h1p, *p_wcp, *p_w1p, *p_w2p;
    cudaGetSymbolAddress((void**)&p_xw,  g_xw);
    cudaGetSymbolAddress((void**)&p_x0p, g_x0p);
    cudaGetSymbolAddress((void**)&p_xrp, g_xrp);
    cudaGetSymbolAddress((void**)&p_h1p, g_h1p);
    cudaGetSymbolAddress((void**)&p_wcp, g_wcp);
    cudaGetSymbolAddress((void**)&p_w1p, g_w1p);
    cudaGetSymbolAddress((void**)&p_w2p, g_w2p);

    cudaFuncSetAttribute(gemm_bf16<0>, cudaFuncAttributeMaxDynamicSharedMemorySize, SMEM_TOT_);
    cudaFuncSetAttribute(gemm_bf16<1>, cudaFuncAttributeMaxDynamicSharedMemorySize, SMEM_TOT_);
    cudaFuncSetAttribute(gemm_bf16<2>, cudaFuncAttributeMaxDynamicSharedMemorySize, SMEM_TOT_);

    // persistent side stream + events (host resources, created once)
    static cudaStream_t s_side = nullptr;
    static cudaEvent_t  s_fork = nullptr, s_join = nullptr;
    if (!s_side) {
        cudaStreamCreateWithFlags(&s_side, cudaStreamNonBlocking);
        cudaEventCreateWithFlags(&s_fork, cudaEventDisableTiming);
        cudaEventCreateWithFlags(&s_join, cudaEventDisableTiming);
    }

    // ---- fork: CSR chain on side stream ----
    cudaEventRecord(s_fork, 0);
    cudaStreamWaitEvent(s_side, s_fork, 0);

    init_kernel  <<<(NG + 255) / 256, 256, 0, s_side>>>();
    detect_kernel<<<(NE + 255) / 256, 256, 0, s_side>>>((const unsigned*)ei);
    count_kernel <<<(NE + 255) / 256, 256, 0, s_side>>>(ei);
    scan1_kernel <<<NBLK, SCAN_BLK, 0, s_side>>>();
    scan2_kernel <<<1, 512, 0, s_side>>>();
    scan3_kernel <<<NBLK, SCAN_BLK, 0, s_side>>>();
    fill_kernel  <<<(NE + 255) / 256, 256, 0, s_side>>>(ei);
    cudaEventRecord(s_join, s_side);

    // ---- main stream: operand prep + GEMM1 (independent of CSR) ----
    split_x0_kernel<<<(NG * F_ / 4 + 255) / 256, 256>>>(x0);
    {
        int tot = F_ * F_ + F_ * H_ + H_ * H_;
        wsplit_all_kernel<<<(tot + 255) / 256, 256>>>(Wc, W1, W2);
    }
    // xw = x0 @ Wc   (fp32 out)  M=80000 N=128 K'=384
    {
        dim3 grid(F_ / 128, NG / 128);
        gemm_bf16<0><<<grid, 256, SMEM_TOT_>>>(p_x0p, p_wcp, nullptr, p_xw, nullptr, F_, F_);
    }

    // ---- join: gather needs CSR + xw ----
    cudaStreamWaitEvent(0, s_join, 0);
    gather_kernel<<<NG / 8, 256>>>(x0, bc);

    // h1 = leaky(xres @ W1 + b1) -> [hi|lo]   M=80000 N=256 K'=384
    {
        dim3 grid(H_ / 128, NG / 128);
        gemm_bf16<1><<<grid, 256, SMEM_TOT_>>>(p_xrp, p_w1p, b1, nullptr, p_h1p, H_, F_);
    }

    // out = leaky(h1 @ W2 + b2) -> fp32   M=80000 N=256 K'=768
    {
        dim3 grid(H_ / 128, NG / 128);
        gemm_bf16<2><<<grid, 256, SMEM_TOT_>>>(p_h1p, p_w2p, b2, out, nullptr, H_, H_);
    }
}